// round 7
// baseline (speedup 1.0000x reference)
#include <cuda_runtime.h>
#include <math.h>

// Problem constants
constexpr int BB = 64;     // batch
constexpr int SS = 2048;   // seq len
constexpr int II = 256;    // input dim
constexpr int HH = 512;    // hidden dim
constexpr int GG = 1536;   // 3*H

// ---------------- device scratch (no allocations allowed) ----------------
__device__ float g_xproj[(size_t)BB * SS * GG];  // precomputed input projections
__device__ float g_hA[BB * HH];
__device__ float g_hB[BB * HH];
__device__ unsigned g_gcnt[4];           // per-group arrival counters (self-resetting)
__device__ volatile unsigned g_ggen[4];  // per-group monotonic generation

// ---------------- f32x2 helpers (FFMA2 — only reachable via PTX) ----------------
__device__ __forceinline__ void ffma2(unsigned long long& d,
                                      unsigned long long a,
                                      unsigned long long b) {
    asm("fma.rn.f32x2 %0, %1, %2, %0;" : "+l"(d) : "l"(a), "l"(b));
}
__device__ __forceinline__ unsigned long long dup2(float x) {
    unsigned long long r;
    asm("mov.b64 %0, {%1, %1};" : "=l"(r) : "f"(x));
    return r;
}
__device__ __forceinline__ float2 unpack2(unsigned long long v) {
    float2 f;
    asm("mov.b64 {%0, %1}, %2;" : "=f"(f.x), "=f"(f.y) : "l"(v));
    return f;
}

// ---------------- Phase 1: x_proj = x @ W + bias ----------------
// M=131072, K=256, N=1536. 128x128 tile, BK=16, 8x8 per thread, 256 threads.
__global__ __launch_bounds__(256) void gemm_xw(const float* __restrict__ A,
                                               const float* __restrict__ Bm,
                                               const float* __restrict__ bias) {
    __shared__ float As[16 * 132];   // transposed, padded
    __shared__ float Bs[16 * 132];
    const int tid = threadIdx.x;
    const int bx = blockIdx.x;   // N tile 0..11
    const int by = blockIdx.y;   // M tile 0..1023
    const int tr = tid >> 4, tc = tid & 15;
    const int rowA0 = by * 128;
    const int colB0 = bx * 128;
    const int iA_r = tid >> 2;          // 0..63
    const int iA_c = (tid & 3) * 4;     // 0,4,8,12
    const int iB_r = tid >> 5;          // 0..7
    const int iB_c = (tid & 31) * 4;    // 0..124

    unsigned long long acc2[8][4];      // 8 rows x 4 col-pairs
#pragma unroll
    for (int i = 0; i < 8; i++)
#pragma unroll
        for (int j = 0; j < 4; j++) acc2[i][j] = 0ull;

    for (int kt = 0; kt < II; kt += 16) {
#pragma unroll
        for (int off = 0; off < 128; off += 64) {
            float4 v = *(const float4*)&A[(size_t)(rowA0 + iA_r + off) * II + kt + iA_c];
            As[(iA_c + 0) * 132 + iA_r + off] = v.x;
            As[(iA_c + 1) * 132 + iA_r + off] = v.y;
            As[(iA_c + 2) * 132 + iA_r + off] = v.z;
            As[(iA_c + 3) * 132 + iA_r + off] = v.w;
        }
#pragma unroll
        for (int off = 0; off < 16; off += 8) {
            float4 v = *(const float4*)&Bm[(size_t)(kt + iB_r + off) * GG + colB0 + iB_c];
            *(float4*)&Bs[(iB_r + off) * 132 + iB_c] = v;
        }
        __syncthreads();
#pragma unroll
        for (int k = 0; k < 16; k++) {
            float rm[8];
            *(float4*)&rm[0] = *(const float4*)&As[k * 132 + tr * 8];
            *(float4*)&rm[4] = *(const float4*)&As[k * 132 + tr * 8 + 4];
            ulonglong2 rb0 = *(const ulonglong2*)&Bs[k * 132 + tc * 8];
            ulonglong2 rb1 = *(const ulonglong2*)&Bs[k * 132 + tc * 8 + 4];
            unsigned long long bb[4] = {rb0.x, rb0.y, rb1.x, rb1.y};
#pragma unroll
            for (int i = 0; i < 8; i++) {
                unsigned long long a = dup2(rm[i]);
#pragma unroll
                for (int j = 0; j < 4; j++) ffma2(acc2[i][j], a, bb[j]);
            }
        }
        __syncthreads();
    }
    // epilogue: +bias, write to g_xproj
#pragma unroll
    for (int i = 0; i < 8; i++) {
        int row = rowA0 + tr * 8 + i;
#pragma unroll
        for (int jp = 0; jp < 2; jp++) {
            int col = colB0 + tc * 8 + jp * 4;
            float4 bv = *(const float4*)&bias[col];
            float2 p0 = unpack2(acc2[i][jp * 2 + 0]);
            float2 p1 = unpack2(acc2[i][jp * 2 + 1]);
            float4 o;
            o.x = p0.x + bv.x;
            o.y = p0.y + bv.y;
            o.z = p1.x + bv.z;
            o.w = p1.y + bv.w;
            *(float4*)&g_xproj[(size_t)row * GG + col] = o;
        }
    }
}

// ---------------- per-group grid barrier (sense-reversing, replay-safe) ----------------
__device__ __forceinline__ void groupbar(int mg, unsigned nctas) {
    __syncthreads();
    if (threadIdx.x == 0) {
        __threadfence();
        unsigned gen = g_ggen[mg];
        if (atomicAdd(&g_gcnt[mg], 1u) == nctas - 1) {
            g_gcnt[mg] = 0;
            __threadfence();
            g_ggen[mg] = gen + 1;
        } else {
            while (g_ggen[mg] == gen) { __nanosleep(32); }
        }
    }
    __syncthreads();
}

// ---------------- Phase 2: persistent recurrence kernel ----------------
// grid = 128 CTAs = 4 batch-groups(16 rows) x 32 feature-groups(16 features).
// FFMA2 mainloop: h duplicated in smem as (h,h) pairs, U pair-interleaved.
constexpr int PU = 1040;             // U2 row pitch (floats)
constexpr int PH = 1048;             // hd row pitch (floats)
constexpr int SM_U2 = 24 * PU;       // 24 col-pairs x 1024 floats (+pad)
constexpr int SM_HD = 16 * PH;       // 16 rows x 1024 floats dup (+pad)
constexpr int SM_RED = 8 * 768;      // per-warp partials
constexpr int SMEM_BYTES = (SM_U2 + SM_HD + SM_RED) * 4;  // 191,488 B

__global__ __launch_bounds__(256, 1) void lstm_rec(const float* __restrict__ U,
                                                   float* __restrict__ out) {
    extern __shared__ float sm[];
    float* U2_s = sm;                 // [jp][2k + {0,1}] = (U[k][col(2jp)], U[k][col(2jp+1)])
    float* hd_s = sm + SM_U2;         // [r][2k + {0,1}] = (h[r][k], h[r][k])
    float* red  = sm + SM_U2 + SM_HD;

    const int tid = threadIdx.x;
    const int bid = blockIdx.x;       // 0..127
    const int mg = bid >> 5;          // 0..3  batch group
    const int ng = bid & 31;          // 0..31 feature group
    const int r0 = mg * 16;           // batch row base
    const int n16 = ng * 16;          // feature base

    // Load U slice pair-interleaved: local col c = gate*16 + f -> global col = gate*512 + n16 + f
    for (int idx = tid; idx < 24 * 512; idx += 256) {
        int jp = idx % 24;
        int k = idx / 24;
        int c0 = 2 * jp, c1 = 2 * jp + 1;
        int colg0 = (c0 >> 4) * HH + n16 + (c0 & 15);
        int colg1 = (c1 >> 4) * HH + n16 + (c1 & 15);
        U2_s[jp * PU + 2 * k]     = U[(size_t)k * GG + colg0];
        U2_s[jp * PU + 2 * k + 1] = U[(size_t)k * GG + colg1];
    }

    const int lane = tid & 31, w = tid >> 5;  // 8 warps: k-split of 64 each
    const int rg = lane >> 3;                 // rows 4*rg .. 4*rg+3
    const int cg = lane & 7;                  // col-pairs 3*cg .. 3*cg+2 (cols 6cg..6cg+5)
    const int kbase = w * 64;

    // Elementwise / reduce mapping: one (row, feature) per thread
    const int er = tid >> 4, ef = tid & 15;

    float* outh = out + (size_t)BB * SS * HH;
    float* outc = outh + BB * HH;

    __syncthreads();  // U2_s ready

    for (int t = 0; t < SS; ++t) {
        const float* hprev = (t & 1) ? g_hB : g_hA;
        float* hnext = (t & 1) ? g_hA : g_hB;

        // Prefetch x_proj gate values for this thread's (row, feature)
        float xp[3];
#pragma unroll
        for (int g = 0; g < 3; g++)
            xp[g] = __ldg(&g_xproj[((size_t)(r0 + er) * SS + t) * GG + g * HH + n16 + ef]);

        // Build duplicated h slice in smem (L1 incoherent across CTAs -> .cg loads)
        if (t == 0) {
            for (int q = tid; q < SM_HD; q += 256) hd_s[q] = 0.f;
        } else {
            for (int q = tid; q < 2048; q += 256) {
                int r = q >> 7, k4 = q & 127;  // 4 k's per float4
                float4 v = __ldcg((const float4*)&hprev[(r0 + r) * HH + k4 * 4]);
                float4 a = make_float4(v.x, v.x, v.y, v.y);
                float4 b = make_float4(v.z, v.z, v.w, v.w);
                *(float4*)&hd_s[r * PH + 8 * k4]     = a;
                *(float4*)&hd_s[r * PH + 8 * k4 + 4] = b;
            }
        }
        __syncthreads();

        // gates partial: acc2[4 rows][3 col-pairs] over this warp's 64-deep K chunk
        unsigned long long acc2[4][3];
#pragma unroll
        for (int i = 0; i < 4; i++)
#pragma unroll
            for (int j = 0; j < 3; j++) acc2[i][j] = 0ull;

#pragma unroll 2
        for (int kk = 0; kk < 64; kk += 2) {
            int k = kbase + kk;
            ulonglong2 ha[4];
#pragma unroll
            for (int i = 0; i < 4; i++)
                ha[i] = *(const ulonglong2*)&hd_s[(4 * rg + i) * PH + 2 * k];
#pragma unroll
            for (int jj = 0; jj < 3; jj++) {
                ulonglong2 ub = *(const ulonglong2*)&U2_s[(3 * cg + jj) * PU + 2 * k];
#pragma unroll
                for (int i = 0; i < 4; i++) {
                    ffma2(acc2[i][jj], ha[i].x, ub.x);
                    ffma2(acc2[i][jj], ha[i].y, ub.y);
                }
            }
        }

        // write per-warp partials (STS.64 per pair)
#pragma unroll
        for (int i = 0; i < 4; i++)
#pragma unroll
            for (int jj = 0; jj < 3; jj++) {
                float2 fv = unpack2(acc2[i][jj]);
                *(float2*)&red[w * 768 + (4 * rg + i) * 48 + 6 * cg + 2 * jj] = fv;
            }
        __syncthreads();

        // fused k-reduce + elementwise: thread owns (er, ef)
        {
            float gate[3];
#pragma unroll
            for (int g = 0; g < 3; g++) {
                float v = xp[g];
                int o = er * 48 + g * 16 + ef;
#pragma unroll
                for (int w2 = 0; w2 < 8; w2++) v += red[w2 * 768 + o];
                gate[g] = v;
            }
            float iv = 1.f / (1.f + __expf(-gate[0]));
            float gv = tanhf(gate[1]);
            float ov = 1.f / (1.f + __expf(-gate[2]));
            float cv = iv * gv;                 // no-forget: c = i*g
            float hv = ov * tanhf(cv);
            int b = r0 + er, jg = n16 + ef;
            __stcg(&hnext[b * HH + jg], hv);    // bypass L1 (cross-CTA visibility)
            out[((size_t)b * SS + t) * HH + jg] = hv;   // hidden_seq
            if (t == SS - 1) {
                outh[b * HH + jg] = hv;         // h_f
                outc[b * HH + jg] = cv;         // c_f
            }
        }

        if (t != SS - 1) groupbar(mg, 32);      // only the 32 CTAs sharing these rows
    }
}

// ---------------- launch ----------------
extern "C" void kernel_launch(void* const* d_in, const int* in_sizes, int n_in,
                              void* d_out, int out_size) {
    const float* x    = (const float*)d_in[0];
    const float* W    = (const float*)d_in[1];
    const float* U    = (const float*)d_in[2];
    const float* bias = (const float*)d_in[3];
    float* out = (float*)d_out;

    cudaFuncSetAttribute(lstm_rec, cudaFuncAttributeMaxDynamicSharedMemorySize, SMEM_BYTES);

    dim3 g1(GG / 128, (BB * SS) / 128);   // 12 x 1024
    gemm_xw<<<g1, 256>>>(x, W, bias);
    lstm_rec<<<128, 256, SMEM_BYTES>>>(U, out);
}

// round 9
// speedup vs baseline: 1.8364x; 1.8364x over previous
#include <cuda_runtime.h>
#include <math.h>

// Problem constants
constexpr int BB = 64;     // batch
constexpr int SS = 2048;   // seq len
constexpr int II = 256;    // input dim
constexpr int HH = 512;    // hidden dim
constexpr int GG = 1536;   // 3*H

// ---------------- device scratch (no allocations allowed) ----------------
__device__ float g_xproj[(size_t)BB * SS * GG];  // precomputed input projections
__device__ float g_hA[BB * HH];
__device__ float g_hB[BB * HH];
__device__ unsigned g_gcnt[4];   // per-group arrival counters (self-resetting)
__device__ unsigned g_ggen[4];   // per-group monotonic generation

// ---------------- acquire/release helpers ----------------
__device__ __forceinline__ unsigned ld_acq(const unsigned* p) {
    unsigned v;
    asm volatile("ld.acquire.gpu.global.u32 %0, [%1];" : "=r"(v) : "l"(p) : "memory");
    return v;
}
__device__ __forceinline__ void st_rel(unsigned* p, unsigned v) {
    asm volatile("st.release.gpu.global.u32 [%0], %1;" :: "l"(p), "r"(v) : "memory");
}

// ---------------- f32x2 helpers (FFMA2 — only reachable via PTX) ----------------
__device__ __forceinline__ void ffma2(unsigned long long& d,
                                      unsigned long long a,
                                      unsigned long long b) {
    asm("fma.rn.f32x2 %0, %1, %2, %0;" : "+l"(d) : "l"(a), "l"(b));
}
__device__ __forceinline__ unsigned long long dup2(float x) {
    unsigned long long r;
    asm("mov.b64 %0, {%1, %1};" : "=l"(r) : "f"(x));
    return r;
}
__device__ __forceinline__ float2 unpack2(unsigned long long v) {
    float2 f;
    asm("mov.b64 {%0, %1}, %2;" : "=f"(f.x), "=f"(f.y) : "l"(v));
    return f;
}

// ---------------- Phase 1: x_proj = x @ W + bias ----------------
// M=131072, K=256, N=1536. 128x128 tile, BK=16, 8x8 per thread, 256 threads.
// Bs consumed via stride-2 LDS.64 (conflict-free); cols per thread: 32*jp + 2*tc.
__global__ __launch_bounds__(256) void gemm_xw(const float* __restrict__ A,
                                               const float* __restrict__ Bm,
                                               const float* __restrict__ bias) {
    __shared__ float As[16 * 132];   // transposed, padded
    __shared__ float Bs[16 * 132];
    const int tid = threadIdx.x;
    const int bx = blockIdx.x;   // N tile 0..11
    const int by = blockIdx.y;   // M tile 0..1023
    const int tr = tid >> 4, tc = tid & 15;
    const int rowA0 = by * 128;
    const int colB0 = bx * 128;
    const int iA_r = tid >> 2;          // 0..63
    const int iA_c = (tid & 3) * 4;     // 0,4,8,12
    const int iB_r = tid >> 5;          // 0..7
    const int iB_c = (tid & 31) * 4;    // 0..124

    unsigned long long acc2[8][4];      // 8 rows x 4 col-pairs (cols 32*jp + 2*tc, +1)
#pragma unroll
    for (int i = 0; i < 8; i++)
#pragma unroll
        for (int j = 0; j < 4; j++) acc2[i][j] = 0ull;

    for (int kt = 0; kt < II; kt += 16) {
#pragma unroll
        for (int off = 0; off < 128; off += 64) {
            float4 v = *(const float4*)&A[(size_t)(rowA0 + iA_r + off) * II + kt + iA_c];
            As[(iA_c + 0) * 132 + iA_r + off] = v.x;
            As[(iA_c + 1) * 132 + iA_r + off] = v.y;
            As[(iA_c + 2) * 132 + iA_r + off] = v.z;
            As[(iA_c + 3) * 132 + iA_r + off] = v.w;
        }
#pragma unroll
        for (int off = 0; off < 16; off += 8) {
            float4 v = *(const float4*)&Bm[(size_t)(kt + iB_r + off) * GG + colB0 + iB_c];
            *(float4*)&Bs[(iB_r + off) * 132 + iB_c] = v;
        }
        __syncthreads();
#pragma unroll
        for (int k = 0; k < 16; k++) {
            float rm[8];
            *(float4*)&rm[0] = *(const float4*)&As[k * 132 + tr * 8];
            *(float4*)&rm[4] = *(const float4*)&As[k * 132 + tr * 8 + 4];
            unsigned long long bb[4];
#pragma unroll
            for (int jp = 0; jp < 4; jp++)
                bb[jp] = *(const unsigned long long*)&Bs[k * 132 + 32 * jp + 2 * tc];
#pragma unroll
            for (int i = 0; i < 8; i++) {
                unsigned long long a = dup2(rm[i]);
#pragma unroll
                for (int j = 0; j < 4; j++) ffma2(acc2[i][j], a, bb[j]);
            }
        }
        __syncthreads();
    }
    // epilogue: +bias, write to g_xproj (float2 per col-pair)
#pragma unroll
    for (int i = 0; i < 8; i++) {
        int row = rowA0 + tr * 8 + i;
#pragma unroll
        for (int jp = 0; jp < 4; jp++) {
            int col = colB0 + 32 * jp + 2 * tc;
            float2 bv = *(const float2*)&bias[col];
            float2 p = unpack2(acc2[i][jp]);
            float2 o;
            o.x = p.x + bv.x;
            o.y = p.y + bv.y;
            *(float2*)&g_xproj[(size_t)row * GG + col] = o;
        }
    }
}

// ---------------- per-group grid barrier (sense-reversing, acquire/release) ----------------
__device__ __forceinline__ void groupbar(int mg, unsigned nctas) {
    __syncthreads();
    if (threadIdx.x == 0) {
        __threadfence();                      // order this CTA's h-store before arrival
        unsigned gen = ld_acq(&g_ggen[mg]);
        if (atomicAdd(&g_gcnt[mg], 1u) == nctas - 1) {
            g_gcnt[mg] = 0;                   // safe: all arrived, none can re-enter yet
            st_rel(&g_ggen[mg], gen + 1);     // release: publishes reset + all h stores
        } else {
            while (ld_acq(&g_ggen[mg]) == gen) { __nanosleep(32); }
        }
    }
    __syncthreads();
}

// ---------------- Phase 2: persistent recurrence kernel ----------------
// grid = 128 CTAs = 4 batch-groups(16 rows) x 32 feature-groups(16 features).
// FFMA2 mainloop: U pair-interleaved in smem (PU=1036: cg-stride ≡ 4 mod 32,
// conflict-free); h natural [16][516] in smem (rows rg+4i: banks distinct),
// h pairs built in registers via dup2 (alu pipe, free).
constexpr int PU   = 1036;           // U2 row pitch (floats); 3*PU ≡ 4 (mod 32)
constexpr int PHN  = 516;            // h row pitch (floats); 516 ≡ 4 (mod 32)
constexpr int SM_U2 = 24 * PU;       // 24 col-pairs x 1024 floats (+pad)
constexpr int SM_H  = 16 * PHN;      // 16 rows x 512 floats (+pad)
constexpr int SM_RED = 8 * 768;      // per-warp partials
constexpr int SMEM_BYTES = (SM_U2 + SM_H + SM_RED) * 4;  // 157,056 B

__global__ __launch_bounds__(256, 1) void lstm_rec(const float* __restrict__ U,
                                                   float* __restrict__ out) {
    extern __shared__ float sm[];
    float* U2_s = sm;                 // [jp][2k + {0,1}] = (U[k][col(2jp)], U[k][col(2jp+1)])
    float* h_s  = sm + SM_U2;         // [r][k] natural
    float* red  = sm + SM_U2 + SM_H;

    const int tid = threadIdx.x;
    const int bid = blockIdx.x;       // 0..127
    const int mg = bid >> 5;          // 0..3  batch group
    const int ng = bid & 31;          // 0..31 feature group
    const int r0 = mg * 16;           // batch row base
    const int n16 = ng * 16;          // feature base

    // Load U slice pair-interleaved: local col c = gate*16 + f -> global col = gate*512 + n16 + f
    for (int idx = tid; idx < 24 * 512; idx += 256) {
        int jp = idx % 24;
        int k = idx / 24;
        int c0 = 2 * jp, c1 = 2 * jp + 1;
        int colg0 = (c0 >> 4) * HH + n16 + (c0 & 15);
        int colg1 = (c1 >> 4) * HH + n16 + (c1 & 15);
        U2_s[jp * PU + 2 * k]     = U[(size_t)k * GG + colg0];
        U2_s[jp * PU + 2 * k + 1] = U[(size_t)k * GG + colg1];
    }

    const int lane = tid & 31, w = tid >> 5;  // 8 warps: k-split of 64 each
    const int rg = lane >> 3;                 // row residue: rows rg, rg+4, rg+8, rg+12
    const int cg = lane & 7;                  // col-pairs 3*cg .. 3*cg+2 (cols 6cg..6cg+5)
    const int kbase = w * 64;

    // Elementwise / reduce mapping: one (row, feature) per thread
    const int er = tid >> 4, ef = tid & 15;

    float* outh = out + (size_t)BB * SS * HH;
    float* outc = outh + BB * HH;

    __syncthreads();  // U2_s ready

    for (int t = 0; t < SS; ++t) {
        const float* hprev = (t & 1) ? g_hB : g_hA;
        float* hnext = (t & 1) ? g_hA : g_hB;

        // Prefetch x_proj gate values for this thread's (row, feature)
        float xp[3];
#pragma unroll
        for (int g = 0; g < 3; g++)
            xp[g] = __ldg(&g_xproj[((size_t)(r0 + er) * SS + t) * GG + g * HH + n16 + ef]);

        // Load h slice (16x512) into smem, natural layout (L1 incoherent -> .cg)
        if (t == 0) {
            for (int q = tid; q < SM_H; q += 256) h_s[q] = 0.f;
        } else {
            for (int q = tid; q < 2048; q += 256) {
                int r = q >> 7, k4 = q & 127;
                float4 v = __ldcg((const float4*)&hprev[(r0 + r) * HH + k4 * 4]);
                *(float4*)&h_s[r * PHN + 4 * k4] = v;   // coalesced, conflict-free
            }
        }
        __syncthreads();

        // gates partial: acc2[4 rows][3 col-pairs] over this warp's 64-deep K chunk
        unsigned long long acc2[4][3];
#pragma unroll
        for (int i = 0; i < 4; i++)
#pragma unroll
            for (int j = 0; j < 3; j++) acc2[i][j] = 0ull;

#pragma unroll 2
        for (int kk = 0; kk < 64; kk += 2) {
            int k = kbase + kk;
            // h pairs for rows rg+4i at k, k+1 (LDS.64, broadcast, banks distinct)
            unsigned long long ha0[4], ha1[4];
#pragma unroll
            for (int i = 0; i < 4; i++) {
                float2 h2 = *(const float2*)&h_s[(rg + 4 * i) * PHN + k];
                ha0[i] = dup2(h2.x);
                ha1[i] = dup2(h2.y);
            }
#pragma unroll
            for (int jj = 0; jj < 3; jj++) {
                ulonglong2 ub = *(const ulonglong2*)&U2_s[(3 * cg + jj) * PU + 2 * k];
#pragma unroll
                for (int i = 0; i < 4; i++) {
                    ffma2(acc2[i][jj], ha0[i], ub.x);
                    ffma2(acc2[i][jj], ha1[i], ub.y);
                }
            }
        }

        // write per-warp partials (STS.64 per pair); rows are rg+4i
#pragma unroll
        for (int i = 0; i < 4; i++)
#pragma unroll
            for (int jj = 0; jj < 3; jj++) {
                float2 fv = unpack2(acc2[i][jj]);
                *(float2*)&red[w * 768 + (rg + 4 * i) * 48 + 6 * cg + 2 * jj] = fv;
            }
        __syncthreads();

        // fused k-reduce + elementwise: thread owns (er, ef)
        {
            float gate[3];
#pragma unroll
            for (int g = 0; g < 3; g++) {
                float v = xp[g];
                int o = er * 48 + g * 16 + ef;
#pragma unroll
                for (int w2 = 0; w2 < 8; w2++) v += red[w2 * 768 + o];
                gate[g] = v;
            }
            float iv = 1.f / (1.f + __expf(-gate[0]));
            float gv = tanhf(gate[1]);
            float ov = 1.f / (1.f + __expf(-gate[2]));
            float cv = iv * gv;                 // no-forget: c = i*g
            float hv = ov * tanhf(cv);
            int b = r0 + er, jg = n16 + ef;
            __stcg(&hnext[b * HH + jg], hv);    // bypass L1 (cross-CTA visibility)
            out[((size_t)b * SS + t) * HH + jg] = hv;   // hidden_seq
            if (t == SS - 1) {
                outh[b * HH + jg] = hv;         // h_f
                outc[b * HH + jg] = cv;         // c_f
            }
        }

        if (t != SS - 1) groupbar(mg, 32);      // only the 32 CTAs sharing these rows
    }
}

// ---------------- launch ----------------
extern "C" void kernel_launch(void* const* d_in, const int* in_sizes, int n_in,
                              void* d_out, int out_size) {
    const float* x    = (const float*)d_in[0];
    const float* W    = (const float*)d_in[1];
    const float* U    = (const float*)d_in[2];
    const float* bias = (const float*)d_in[3];
    float* out = (float*)d_out;

    cudaFuncSetAttribute(lstm_rec, cudaFuncAttributeMaxDynamicSharedMemorySize, SMEM_BYTES);

    dim3 g1(GG / 128, (BB * SS) / 128);   // 12 x 1024
    gemm_xw<<<g1, 256>>>(x, W, bias);
    lstm_rec<<<128, 256, SMEM_BYTES>>>(U, out);
}

// round 10
// speedup vs baseline: 1.8759x; 1.0215x over previous
#include <cuda_runtime.h>
#include <math.h>

// Problem constants
constexpr int BB = 64;     // batch
constexpr int SS = 2048;   // seq len
constexpr int II = 256;    // input dim
constexpr int HH = 512;    // hidden dim
constexpr int GG = 1536;   // 3*H

// ---------------- device scratch (no allocations allowed) ----------------
__device__ float g_xproj[(size_t)BB * SS * GG];  // precomputed input projections
__device__ float g_hA[BB * HH];
__device__ float g_hB[BB * HH];
__device__ unsigned g_gcnt[4];   // per-group arrival counters (self-resetting)
__device__ unsigned g_ggen[4];   // per-group monotonic generation

// ---------------- acquire/release helpers ----------------
__device__ __forceinline__ unsigned ld_acq(const unsigned* p) {
    unsigned v;
    asm volatile("ld.acquire.gpu.global.u32 %0, [%1];" : "=r"(v) : "l"(p) : "memory");
    return v;
}
__device__ __forceinline__ void st_rel(unsigned* p, unsigned v) {
    asm volatile("st.release.gpu.global.u32 [%0], %1;" :: "l"(p), "r"(v) : "memory");
}

// ---------------- f32x2 helpers (FFMA2 — only reachable via PTX) ----------------
__device__ __forceinline__ void ffma2(unsigned long long& d,
                                      unsigned long long a,
                                      unsigned long long b) {
    asm("fma.rn.f32x2 %0, %1, %2, %0;" : "+l"(d) : "l"(a), "l"(b));
}
__device__ __forceinline__ unsigned long long dup2(float x) {
    unsigned long long r;
    asm("mov.b64 %0, {%1, %1};" : "=l"(r) : "f"(x));
    return r;
}
__device__ __forceinline__ float2 unpack2(unsigned long long v) {
    float2 f;
    asm("mov.b64 {%0, %1}, %2;" : "=f"(f.x), "=f"(f.y) : "l"(v));
    return f;
}

// Fast, NaN-safe sigmoid/tanh (MUFU-based; error << 1e-3 tolerance)
__device__ __forceinline__ float fsigmoid(float z) {
    return __fdividef(1.f, 1.f + __expf(-z));
}
__device__ __forceinline__ float ftanh(float x) {
    return fmaf(2.f, fsigmoid(2.f * x), -1.f);
}

// ---------------- Phase 1: x_proj = x @ W + bias ----------------
// (unchanged from round 9 — known good, ~1.4 ms)
__global__ __launch_bounds__(256) void gemm_xw(const float* __restrict__ A,
                                               const float* __restrict__ Bm,
                                               const float* __restrict__ bias) {
    __shared__ float As[16 * 132];   // transposed, padded
    __shared__ float Bs[16 * 132];
    const int tid = threadIdx.x;
    const int bx = blockIdx.x;   // N tile 0..11
    const int by = blockIdx.y;   // M tile 0..1023
    const int tr = tid >> 4, tc = tid & 15;
    const int rowA0 = by * 128;
    const int colB0 = bx * 128;
    const int iA_r = tid >> 2;
    const int iA_c = (tid & 3) * 4;
    const int iB_r = tid >> 5;
    const int iB_c = (tid & 31) * 4;

    unsigned long long acc2[8][4];
#pragma unroll
    for (int i = 0; i < 8; i++)
#pragma unroll
        for (int j = 0; j < 4; j++) acc2[i][j] = 0ull;

    for (int kt = 0; kt < II; kt += 16) {
#pragma unroll
        for (int off = 0; off < 128; off += 64) {
            float4 v = *(const float4*)&A[(size_t)(rowA0 + iA_r + off) * II + kt + iA_c];
            As[(iA_c + 0) * 132 + iA_r + off] = v.x;
            As[(iA_c + 1) * 132 + iA_r + off] = v.y;
            As[(iA_c + 2) * 132 + iA_r + off] = v.z;
            As[(iA_c + 3) * 132 + iA_r + off] = v.w;
        }
#pragma unroll
        for (int off = 0; off < 16; off += 8) {
            float4 v = *(const float4*)&Bm[(size_t)(kt + iB_r + off) * GG + colB0 + iB_c];
            *(float4*)&Bs[(iB_r + off) * 132 + iB_c] = v;
        }
        __syncthreads();
#pragma unroll
        for (int k = 0; k < 16; k++) {
            float rm[8];
            *(float4*)&rm[0] = *(const float4*)&As[k * 132 + tr * 8];
            *(float4*)&rm[4] = *(const float4*)&As[k * 132 + tr * 8 + 4];
            unsigned long long bb[4];
#pragma unroll
            for (int jp = 0; jp < 4; jp++)
                bb[jp] = *(const unsigned long long*)&Bs[k * 132 + 32 * jp + 2 * tc];
#pragma unroll
            for (int i = 0; i < 8; i++) {
                unsigned long long a = dup2(rm[i]);
#pragma unroll
                for (int j = 0; j < 4; j++) ffma2(acc2[i][j], a, bb[j]);
            }
        }
        __syncthreads();
    }
#pragma unroll
    for (int i = 0; i < 8; i++) {
        int row = rowA0 + tr * 8 + i;
#pragma unroll
        for (int jp = 0; jp < 4; jp++) {
            int col = colB0 + 32 * jp + 2 * tc;
            float2 bv = *(const float2*)&bias[col];
            float2 p = unpack2(acc2[i][jp]);
            float2 o;
            o.x = p.x + bv.x;
            o.y = p.y + bv.y;
            *(float2*)&g_xproj[(size_t)row * GG + col] = o;
        }
    }
}

// ---------------- per-group grid barrier (sense-reversing, acquire/release) ----------------
__device__ __forceinline__ void groupbar(int mg, unsigned nctas) {
    __syncthreads();
    if (threadIdx.x == 0) {
        __threadfence();                      // order this CTA's h-store before arrival
        unsigned gen = ld_acq(&g_ggen[mg]);
        if (atomicAdd(&g_gcnt[mg], 1u) == nctas - 1) {
            g_gcnt[mg] = 0;                   // safe: all arrived, none can re-enter yet
            st_rel(&g_ggen[mg], gen + 1);     // release: publishes reset + all h stores
        } else {
            while (ld_acq(&g_ggen[mg]) == gen) { __nanosleep(32); }
        }
    }
    __syncthreads();
}

// ---------------- Phase 2: persistent recurrence kernel ----------------
// grid = 128 CTAs = 4 batch-groups(16 rows) x 32 feature-groups(16 features).
// 512 threads / 16 warps: k-split 32/warp (4 warps per SMSP for latency hiding).
// Lane tile: 2 rows x 6 col-pairs (FFMA2). Bank-conflict-free (see analysis).
constexpr int NT   = 512;            // threads per CTA
constexpr int PU   = 1036;           // U2 row pitch; 6*PU ≡ 8 (mod 32) -> cgi quads 0,8,16,24
constexpr int PHN  = 516;            // h row pitch; 516 ≡ 4 (mod 32) -> 8 distinct bank-pairs
constexpr int SM_U2 = 24 * PU;       // 24 col-pairs x 1024 floats (+pad)
constexpr int SM_H  = 16 * PHN;      // 16 rows x 512 floats (+pad)
constexpr int SM_RED = 16 * 768;     // per-warp partials (16 warps)
constexpr int SMEM_BYTES = (SM_U2 + SM_H + SM_RED) * 4;  // 181,632 B

__global__ __launch_bounds__(NT, 1) void lstm_rec(const float* __restrict__ U,
                                                  float* __restrict__ out) {
    extern __shared__ float sm[];
    float* U2_s = sm;                 // [jp][2k + {0,1}] = (U[k][col(2jp)], U[k][col(2jp+1)])
    float* h_s  = sm + SM_U2;         // [r][k] natural
    float* red  = sm + SM_U2 + SM_H;

    const int tid = threadIdx.x;
    const int bid = blockIdx.x;       // 0..127
    const int mg = bid >> 5;          // 0..3  batch group
    const int ng = bid & 31;          // 0..31 feature group
    const int r0 = mg * 16;           // batch row base
    const int n16 = ng * 16;          // feature base

    // Load U slice pair-interleaved: local col c = gate*16 + f -> global col = gate*512 + n16 + f
    for (int idx = tid; idx < 24 * 512; idx += NT) {
        int jp = idx % 24;
        int k = idx / 24;
        int c0 = 2 * jp, c1 = 2 * jp + 1;
        int colg0 = (c0 >> 4) * HH + n16 + (c0 & 15);
        int colg1 = (c1 >> 4) * HH + n16 + (c1 & 15);
        U2_s[jp * PU + 2 * k]     = U[(size_t)k * GG + colg0];
        U2_s[jp * PU + 2 * k + 1] = U[(size_t)k * GG + colg1];
    }

    const int lane = tid & 31, w = tid >> 5;  // 16 warps: k-split of 32 each
    const int rgi = lane & 7;                 // rows rgi, rgi+8
    const int cgi = lane >> 3;                // col-pairs 6*cgi .. 6*cgi+5
    const int kbase = w * 32;

    // Elementwise / reduce mapping: threads 0..255 own one (row, feature)
    const int er = (tid & 255) >> 4, ef = tid & 15;
    const bool do_elem = (tid < 256);

    float* outh = out + (size_t)BB * SS * HH;
    float* outc = outh + BB * HH;

    __syncthreads();  // U2_s ready

    for (int t = 0; t < SS; ++t) {
        const float* hprev = (t & 1) ? g_hB : g_hA;
        float* hnext = (t & 1) ? g_hA : g_hB;

        // Prefetch x_proj gate values for this thread's (row, feature)
        float xp[3];
        if (do_elem) {
#pragma unroll
            for (int g = 0; g < 3; g++)
                xp[g] = __ldg(&g_xproj[((size_t)(r0 + er) * SS + t) * GG + g * HH + n16 + ef]);
        }

        // Load h slice (16x512) into smem, natural layout (L1 incoherent -> .cg)
        if (t == 0) {
            for (int q = tid; q < SM_H; q += NT) h_s[q] = 0.f;
        } else {
#pragma unroll
            for (int it = 0; it < 4; it++) {
                int q = tid + it * NT;
                int r = q >> 7, k4 = q & 127;
                float4 v = __ldcg((const float4*)&hprev[(r0 + r) * HH + k4 * 4]);
                *(float4*)&h_s[r * PHN + 4 * k4] = v;
            }
        }
        __syncthreads();

        // gates partial: acc2[2 rows][6 col-pairs] over this warp's 32-deep K chunk
        unsigned long long acc2[2][6];
#pragma unroll
        for (int i = 0; i < 2; i++)
#pragma unroll
            for (int j = 0; j < 6; j++) acc2[i][j] = 0ull;

#pragma unroll 4
        for (int kk = 0; kk < 32; kk += 2) {
            int k = kbase + kk;
            float2 h0 = *(const float2*)&h_s[rgi * PHN + k];
            float2 h1 = *(const float2*)&h_s[(rgi + 8) * PHN + k];
            unsigned long long ha00 = dup2(h0.x), ha01 = dup2(h0.y);
            unsigned long long ha10 = dup2(h1.x), ha11 = dup2(h1.y);
#pragma unroll
            for (int jj = 0; jj < 6; jj++) {
                ulonglong2 ub = *(const ulonglong2*)&U2_s[(6 * cgi + jj) * PU + 2 * k];
                ffma2(acc2[0][jj], ha00, ub.x);
                ffma2(acc2[0][jj], ha01, ub.y);
                ffma2(acc2[1][jj], ha10, ub.x);
                ffma2(acc2[1][jj], ha11, ub.y);
            }
        }

        // write per-warp partials (STS.64 per pair); rows rgi, rgi+8
#pragma unroll
        for (int i = 0; i < 2; i++) {
            int r = rgi + 8 * i;
#pragma unroll
            for (int jj = 0; jj < 6; jj++) {
                float2 fv = unpack2(acc2[i][jj]);
                *(float2*)&red[w * 768 + r * 48 + 12 * cgi + 2 * jj] = fv;
            }
        }
        __syncthreads();

        // fused k-reduce (16 partials) + elementwise: threads 0..255
        if (do_elem) {
            float gate[3];
#pragma unroll
            for (int g = 0; g < 3; g++) {
                float v = xp[g];
                int o = er * 48 + g * 16 + ef;
#pragma unroll
                for (int w2 = 0; w2 < 16; w2++) v += red[w2 * 768 + o];
                gate[g] = v;
            }
            float iv = fsigmoid(gate[0]);
            float gv = ftanh(gate[1]);
            float ov = fsigmoid(gate[2]);
            float cv = iv * gv;                 // no-forget: c = i*g
            float hv = ov * ftanh(cv);
            int b = r0 + er, jg = n16 + ef;
            __stcg(&hnext[b * HH + jg], hv);    // bypass L1 (cross-CTA visibility)
            out[((size_t)b * SS + t) * HH + jg] = hv;   // hidden_seq
            if (t == SS - 1) {
                outh[b * HH + jg] = hv;         // h_f
                outc[b * HH + jg] = cv;         // c_f
            }
        }

        if (t != SS - 1) groupbar(mg, 32);      // only the 32 CTAs sharing these rows
    }
}

// ---------------- launch ----------------
extern "C" void kernel_launch(void* const* d_in, const int* in_sizes, int n_in,
                              void* d_out, int out_size) {
    const float* x    = (const float*)d_in[0];
    const float* W    = (const float*)d_in[1];
    const float* U    = (const float*)d_in[2];
    const float* bias = (const float*)d_in[3];
    float* out = (float*)d_out;

    cudaFuncSetAttribute(lstm_rec, cudaFuncAttributeMaxDynamicSharedMemorySize, SMEM_BYTES);

    dim3 g1(GG / 128, (BB * SS) / 128);   // 12 x 1024
    gemm_xw<<<g1, 256>>>(x, W, bias);
    lstm_rec<<<128, NT, SMEM_BYTES>>>(U, out);
}